// round 14
// baseline (speedup 1.0000x reference)
#include <cuda_runtime.h>
#include <math.h>

// Sinkhorn distance, N=M=4096, D=256, EPS=0.1, 100 iterations.
// R13: R10 lazy-LSE passes + SYMMETRIC flag-array grid barrier (every CTA
// polls all arrival flags itself; no central release word; monotonic tokens)
// + GEMM k-tile register prefetch.

#define NN 4096
#define KK 256
#define SCALEF 14.4269504088896340736f   // log2(e)/EPS
#define NEG_BIG (-1e30f)
#define THREADS 1024
#define NBMAX 160
#define N_ITER 100
#define TH_SKIP 40.f
#define TH_LO   10.f
#define TH_HI   50.f
#define CLAMP   80.f

__device__ __align__(16) float g_C2[(size_t)NN * NN];     // 64 MB: C * SCALEF
__device__ __align__(16) float g_u[NN];
__device__ __align__(16) float g_v[NN];
__device__ __align__(16) float g_mu[NN];                  // row max estimate (t-domain)
__device__ __align__(16) float g_mv[NN];                  // col max estimate
__device__ float g_xs[NN];
__device__ float g_ys[NN];
__device__ double g_dpart[NBMAX];

// ---- symmetric flag-array grid barrier (monotonic tokens, no reset) ----
__device__ volatile unsigned g_arrive[NBMAX];

__device__ __forceinline__ float ex2f(float x) {
    float r; asm("ex2.approx.ftz.f32 %0, %1;" : "=f"(r) : "f"(x)); return r;
}
__device__ __forceinline__ float lg2f(float x) {
    float r; asm("lg2.approx.ftz.f32 %0, %1;" : "=f"(r) : "f"(x)); return r;
}

// Every CTA: 1 STG arrival, then its warp 0 polls ALL NB flags (5 per lane).
// Monotonic tokens -> no reset race. Post-poll fence by thread 0 gives the
// block acquire semantics (same pattern proven correct in R5-R11).
__device__ __forceinline__ void grid_sync(int NB, unsigned token) {
    __syncthreads();
    if (threadIdx.x == 0) {
        __threadfence();
        g_arrive[blockIdx.x] = token;
    }
    if (threadIdx.x < 32) {
        for (int s = threadIdx.x; s < NB; s += 32) {
            while (g_arrive[s] < token) { }
        }
        __syncwarp();
        if (threadIdx.x == 0) __threadfence();
    }
    __syncthreads();
}

// ---------------------------------------------------------------------------
__global__ __launch_bounds__(256) void sqnorm_kernel(const float* __restrict__ X,
                                                     const float* __restrict__ Y) {
    int gw = (blockIdx.x * 256 + threadIdx.x) >> 5;
    int lane = threadIdx.x & 31;
    const float* src = (gw < NN) ? (X + (size_t)gw * KK) : (Y + (size_t)(gw - NN) * KK);
    float s = 0.f;
    #pragma unroll
    for (int c = 0; c < KK; c += 32) {
        float a = src[c + lane];
        s = fmaf(a, a, s);
    }
    #pragma unroll
    for (int o = 16; o; o >>= 1) s += __shfl_xor_sync(0xffffffffu, s, o);
    if (lane == 0) {
        if (gw < NN) g_xs[gw] = s; else g_ys[gw - NN] = s;
    }
}

__global__ void init_kernel() {
    int i = blockIdx.x * 256 + threadIdx.x;
    if (i < NN) { g_v[i] = 0.f; g_mu[i] = NEG_BIG; g_mv[i] = NEG_BIG; }
    if (i < NBMAX) g_arrive[i] = 0;
}

// ---------------------------------------------------------------------------
// C2[i][j] = (|x_i|^2 + |y_j|^2 - 2 x_i . y_j) * SCALEF  (fp32 FFMA GEMM)
// k-tile register prefetch issued before the FFMA block.
__global__ __launch_bounds__(256) void gemm_kernel(const float* __restrict__ X,
                                                   const float* __restrict__ Y) {
    __shared__ float As[8][128];
    __shared__ float Bs[8][128];
    const int tid = threadIdx.x;
    const int bx = blockIdx.x;
    const int by = blockIdx.y;
    const int ar = tid >> 1;
    const int ak = (tid & 1) * 4;
    const int tx = tid & 15;
    const int ty = tid >> 4;

    const float* xp = X + (size_t)(by * 128 + ar) * KK + ak;
    const float* yp = Y + (size_t)(bx * 128 + ar) * KK + ak;

    float acc[8][8];
    #pragma unroll
    for (int i = 0; i < 8; ++i)
        #pragma unroll
        for (int j = 0; j < 8; ++j) acc[i][j] = 0.f;

    float4 av = *(const float4*)(xp);
    float4 bv = *(const float4*)(yp);

    for (int kt = 0; kt < KK; kt += 8) {
        __syncthreads();
        As[ak + 0][ar] = av.x; As[ak + 1][ar] = av.y;
        As[ak + 2][ar] = av.z; As[ak + 3][ar] = av.w;
        Bs[ak + 0][ar] = bv.x; Bs[ak + 1][ar] = bv.y;
        Bs[ak + 2][ar] = bv.z; Bs[ak + 3][ar] = bv.w;
        __syncthreads();
        if (kt + 8 < KK) {
            av = *(const float4*)(xp + kt + 8);   // prefetch overlaps compute
            bv = *(const float4*)(yp + kt + 8);
        }
        #pragma unroll
        for (int k = 0; k < 8; ++k) {
            float a[8], b[8];
            *(float4*)(a)     = *(const float4*)&As[k][ty * 8];
            *(float4*)(a + 4) = *(const float4*)&As[k][ty * 8 + 4];
            *(float4*)(b)     = *(const float4*)&Bs[k][tx * 8];
            *(float4*)(b + 4) = *(const float4*)&Bs[k][tx * 8 + 4];
            #pragma unroll
            for (int i = 0; i < 8; ++i)
                #pragma unroll
                for (int j = 0; j < 8; ++j)
                    acc[i][j] = fmaf(a[i], b[j], acc[i][j]);
        }
    }

    const int gi0 = by * 128 + ty * 8;
    const int gj0 = bx * 128 + tx * 8;
    float yv[8];
    #pragma unroll
    for (int j = 0; j < 8; ++j) yv[j] = g_ys[gj0 + j];
    #pragma unroll
    for (int i = 0; i < 8; ++i) {
        float xs = g_xs[gi0 + i];
        float4 o0, o1;
        o0.x = (xs + yv[0] - 2.f * acc[i][0]) * SCALEF;
        o0.y = (xs + yv[1] - 2.f * acc[i][1]) * SCALEF;
        o0.z = (xs + yv[2] - 2.f * acc[i][2]) * SCALEF;
        o0.w = (xs + yv[3] - 2.f * acc[i][3]) * SCALEF;
        o1.x = (xs + yv[4] - 2.f * acc[i][4]) * SCALEF;
        o1.y = (xs + yv[5] - 2.f * acc[i][5]) * SCALEF;
        o1.z = (xs + yv[6] - 2.f * acc[i][6]) * SCALEF;
        o1.w = (xs + yv[7] - 2.f * acc[i][7]) * SCALEF;
        float* dst = g_C2 + (size_t)(gi0 + i) * NN + gj0;
        *(float4*)(dst)     = o0;
        *(float4*)(dst + 4) = o1;
    }
}

// ---------------------------------------------------------------------------
__global__ __launch_bounds__(THREADS, 1) void sinkhorn_persistent(int NB, float* __restrict__ out) {
    const int tid = threadIdx.x;
    const int bid = blockIdx.x;
    const int lane = tid & 31;
    const int wid = tid >> 5;
    unsigned tok = 0;

    __shared__ float svec[NN];          // 16 KB: dual-potential cache
    __shared__ float sm_m[32][33];
    __shared__ float sm_s[32][33];
    __shared__ float sshift[32];
    __shared__ int   sfail;
    __shared__ float sred[32];

    for (int it = 0; it < N_ITER; ++it) {
        // ---- u-pass: warp-per-row, lazy LSE ----
        for (int i = tid; i < NN; i += THREADS) svec[i] = g_v[i];
        __syncthreads();

        for (int row = bid + wid * NB; row < NN; row += 32 * NB) {
            const float* Crow = g_C2 + (size_t)row * NN;
            float shift = g_mu[row];
            float Mrun, Ssum;
            #pragma unroll 1
            for (int attempt = 0; attempt < 4; ++attempt) {
                float mrun = NEG_BIG, s = 0.f;
                const float thr = shift - TH_SKIP;
                #pragma unroll 1
                for (int c0 = 0; c0 < NN; c0 += 256) {
                    int c = c0 + lane * 4;
                    float4 C0 = __ldg((const float4*)(Crow + c));
                    float4 C1 = __ldg((const float4*)(Crow + c + 128));
                    float4 V0 = *(const float4*)&svec[c];
                    float4 V1 = *(const float4*)&svec[c + 128];
                    float t0 = V0.x - C0.x, t1 = V0.y - C0.y;
                    float t2 = V0.z - C0.z, t3 = V0.w - C0.w;
                    float t4 = V1.x - C1.x, t5 = V1.y - C1.y;
                    float t6 = V1.z - C1.z, t7 = V1.w - C1.w;
                    float mc = fmaxf(fmaxf(fmaxf(t0, t1), fmaxf(t2, t3)),
                                     fmaxf(fmaxf(t4, t5), fmaxf(t6, t7)));
                    mrun = fmaxf(mrun, mc);
                    if (__any_sync(0xffffffffu, mc >= thr)) {
                        s += ((ex2f(fminf(t0 - shift, CLAMP)) + ex2f(fminf(t1 - shift, CLAMP)))
                            + (ex2f(fminf(t2 - shift, CLAMP)) + ex2f(fminf(t3 - shift, CLAMP))))
                           + ((ex2f(fminf(t4 - shift, CLAMP)) + ex2f(fminf(t5 - shift, CLAMP)))
                            + (ex2f(fminf(t6 - shift, CLAMP)) + ex2f(fminf(t7 - shift, CLAMP))));
                    }
                }
                Mrun = mrun; Ssum = s;
                #pragma unroll
                for (int o = 16; o; o >>= 1) {
                    Mrun = fmaxf(Mrun, __shfl_xor_sync(0xffffffffu, Mrun, o));
                    Ssum += __shfl_xor_sync(0xffffffffu, Ssum, o);
                }
                if (Mrun >= shift - TH_LO && Mrun <= shift + TH_HI) break;
                shift = Mrun;
            }
            if (lane == 0) {
                g_u[row] = -(shift + lg2f(Ssum));
                g_mu[row] = Mrun;
            }
        }
        grid_sync(NB, ++tok);

        // ---- v-pass: CTA owns 32 columns; lazy LSE; shift common per column ----
        for (int i = tid; i < NN; i += THREADS) svec[i] = g_u[i];
        __syncthreads();
        for (int g = bid; g < NN / 32; g += NB) {
            const int j0 = g << 5;
            const int c = lane;
            const int r = wid;
            if (tid < 32) sshift[tid] = g_mv[j0 + tid];
            if (tid == 0) sfail = 0;
            __syncthreads();
            #pragma unroll 1
            for (int attempt = 0; attempt < 4; ++attempt) {
                float shift = sshift[c];
                const float thr = shift - TH_SKIP;
                float mrun = NEG_BIG, s = 0.f;
                #pragma unroll 1
                for (int q0 = 0; q0 < NN; q0 += 512) {
                    const float* p = g_C2 + (size_t)(q0 + r) * NN + j0 + c;
                    const float* up = &svec[q0 + r];
                    float t[16];
                    #pragma unroll
                    for (int k = 0; k < 16; ++k)
                        t[k] = up[k << 5] - __ldg(p + ((size_t)k << 5) * NN);
                    float mc = t[0];
                    #pragma unroll
                    for (int k = 1; k < 16; ++k) mc = fmaxf(mc, t[k]);
                    mrun = fmaxf(mrun, mc);
                    if (__any_sync(0xffffffffu, mc >= thr)) {
                        float e = 0.f;
                        #pragma unroll
                        for (int k = 0; k < 16; ++k)
                            e += ex2f(fminf(t[k] - shift, CLAMP));
                        s += e;
                    }
                }
                sm_m[r][c] = mrun;
                sm_s[r][c] = s;
                __syncthreads();
                {   // warp wid merges column wid (plain sum: common shift)
                    float mm = sm_m[lane][wid];
                    float ss = sm_s[lane][wid];
                    #pragma unroll
                    for (int o = 16; o; o >>= 1) {
                        mm = fmaxf(mm, __shfl_xor_sync(0xffffffffu, mm, o));
                        ss += __shfl_xor_sync(0xffffffffu, ss, o);
                    }
                    float sc = sshift[wid];
                    bool ok = (mm >= sc - TH_LO && mm <= sc + TH_HI);
                    if (lane == 0) {
                        if (ok) {
                            g_v[j0 + wid] = -(sc + lg2f(ss));
                            g_mv[j0 + wid] = mm;
                        } else {
                            sshift[wid] = mm;
                            sfail = 1;
                        }
                    }
                }
                __syncthreads();
                if (!sfail) break;
                if (tid == 0) sfail = 0;
                __syncthreads();
            }
            __syncthreads();
        }
        grid_sync(NB, ++tok);
    }

    // ---- final cost: sum P*C / N  (warp-per-row, full exp) ----
    {
        for (int i = tid; i < NN; i += THREADS) svec[i] = g_v[i];
        __syncthreads();
        float acc = 0.f;
        for (int row = bid + wid * NB; row < NN; row += 32 * NB) {
            const float u2 = g_u[row];
            const float* Crow = g_C2 + (size_t)row * NN;
            #pragma unroll 4
            for (int c0 = 0; c0 < NN; c0 += 128) {
                int cc = c0 + lane * 4;
                float4 C4 = __ldg((const float4*)(Crow + cc));
                float4 V4 = *(const float4*)&svec[cc];
                acc = fmaf(ex2f(u2 + V4.x - C4.x), C4.x, acc);
                acc = fmaf(ex2f(u2 + V4.y - C4.y), C4.y, acc);
                acc = fmaf(ex2f(u2 + V4.z - C4.z), C4.z, acc);
                acc = fmaf(ex2f(u2 + V4.w - C4.w), C4.w, acc);
            }
        }
        #pragma unroll
        for (int o = 16; o; o >>= 1) acc += __shfl_xor_sync(0xffffffffu, acc, o);
        __syncthreads();
        if (lane == 0) sred[wid] = acc;
        __syncthreads();
        if (wid == 0) {
            float s = sred[lane];
            #pragma unroll
            for (int o = 16; o; o >>= 1) s += __shfl_xor_sync(0xffffffffu, s, o);
            if (lane == 0) g_dpart[bid] = (double)s;
        }
        grid_sync(NB, ++tok);
        if (bid == 0 && tid == 0) {
            double S = 0.0;
            for (int b = 0; b < NB; ++b) S += g_dpart[b];
            out[0] = (float)(S / ((double)SCALEF * (double)NN));
        }
    }
}

// ---------------------------------------------------------------------------
extern "C" void kernel_launch(void* const* d_in, const int* in_sizes, int n_in,
                              void* d_out, int out_size) {
    const float* x = (const float*)d_in[0];
    const float* y = (const float*)d_in[1];
    float* out = (float*)d_out;

    int dev = 0;
    cudaGetDevice(&dev);
    int sm = 148;
    cudaDeviceGetAttribute(&sm, cudaDevAttrMultiProcessorCount, dev);
    int NB = sm < NBMAX ? sm : NBMAX;

    sqnorm_kernel<<<1024, 256>>>(x, y);
    init_kernel<<<16, 256>>>();
    gemm_kernel<<<dim3(32, 32), 256>>>(x, y);
    sinkhorn_persistent<<<NB, THREADS>>>(NB, out);
}

// round 15
// speedup vs baseline: 1.0928x; 1.0928x over previous
#include <cuda_runtime.h>
#include <cuda_fp16.h>
#include <math.h>

// Sinkhorn distance, N=M=4096, D=256, EPS=0.1, 100 iterations.
// R15: lazy-LSE with fp16 shadow copy of C for the max-scan (32 MB; both
// copies L2-resident). Survivor chunks re-read exact fp32 C -> numerics
// identical to R11. Atomic grid barrier (R11, proven). GEMM k-prefetch.

#define NN 4096
#define KK 256
#define SCALEF 14.4269504088896340736f   // log2(e)/EPS
#define NEG_BIG (-1e30f)
#define THREADS 1024
#define NBMAX 160
#define N_ITER 100
#define TH_SKIP 56.f     // skip threshold incl. fp16 scan-error margin
#define TH_LO   30.f
#define TH_HI   50.f
#define CLAMP   80.f

__device__ __align__(16) float g_C2[(size_t)NN * NN];     // 64 MB fp32
__device__ __align__(16) __half g_Ch[(size_t)NN * NN];    // 32 MB fp16 shadow
__device__ __align__(16) float g_u[NN];
__device__ __align__(16) float g_v[NN];
__device__ __align__(16) float g_mu[NN];
__device__ __align__(16) float g_mv[NN];
__device__ float g_xs[NN];
__device__ float g_ys[NN];
__device__ double g_dpart[NBMAX];

__device__ unsigned g_bar_count;
__device__ volatile unsigned g_bar_gen;

union H8 { uint4 u; __half2 h[4]; };

__device__ __forceinline__ float ex2f(float x) {
    float r; asm("ex2.approx.ftz.f32 %0, %1;" : "=f"(r) : "f"(x)); return r;
}
__device__ __forceinline__ float lg2f(float x) {
    float r; asm("lg2.approx.ftz.f32 %0, %1;" : "=f"(r) : "f"(x)); return r;
}

// R11 atomic barrier (single-line spin, L2-broadcast-friendly; proven).
__device__ __forceinline__ void grid_sync(int NB) {
    __syncthreads();
    if (threadIdx.x == 0) {
        unsigned gen = g_bar_gen;
        __threadfence();
        unsigned t = atomicAdd(&g_bar_count, 1u);
        if (t == (unsigned)(NB - 1)) {
            g_bar_count = 0;
            __threadfence();
            g_bar_gen = gen + 1;
        } else {
            while (g_bar_gen == gen) { }
        }
        __threadfence();
    }
    __syncthreads();
}

// ---------------------------------------------------------------------------
__global__ __launch_bounds__(256) void sqnorm_kernel(const float* __restrict__ X,
                                                     const float* __restrict__ Y) {
    int gw = (blockIdx.x * 256 + threadIdx.x) >> 5;
    int lane = threadIdx.x & 31;
    const float* src = (gw < NN) ? (X + (size_t)gw * KK) : (Y + (size_t)(gw - NN) * KK);
    float s = 0.f;
    #pragma unroll
    for (int c = 0; c < KK; c += 32) {
        float a = src[c + lane];
        s = fmaf(a, a, s);
    }
    #pragma unroll
    for (int o = 16; o; o >>= 1) s += __shfl_xor_sync(0xffffffffu, s, o);
    if (lane == 0) {
        if (gw < NN) g_xs[gw] = s; else g_ys[gw - NN] = s;
    }
}

__global__ void init_kernel() {
    int i = blockIdx.x * 256 + threadIdx.x;
    if (i < NN) { g_v[i] = 0.f; g_mu[i] = NEG_BIG; g_mv[i] = NEG_BIG; }
    if (i == 0) { g_bar_count = 0; g_bar_gen = 0; }
}

// ---------------------------------------------------------------------------
// C2 = (|x|^2 + |y|^2 - 2 x.y) * SCALEF; fp32 + fp16 shadow stores.
__global__ __launch_bounds__(256) void gemm_kernel(const float* __restrict__ X,
                                                   const float* __restrict__ Y) {
    __shared__ float As[8][128];
    __shared__ float Bs[8][128];
    const int tid = threadIdx.x;
    const int bx = blockIdx.x;
    const int by = blockIdx.y;
    const int ar = tid >> 1;
    const int ak = (tid & 1) * 4;
    const int tx = tid & 15;
    const int ty = tid >> 4;

    const float* xp = X + (size_t)(by * 128 + ar) * KK + ak;
    const float* yp = Y + (size_t)(bx * 128 + ar) * KK + ak;

    float acc[8][8];
    #pragma unroll
    for (int i = 0; i < 8; ++i)
        #pragma unroll
        for (int j = 0; j < 8; ++j) acc[i][j] = 0.f;

    float4 av = *(const float4*)(xp);
    float4 bv = *(const float4*)(yp);

    for (int kt = 0; kt < KK; kt += 8) {
        __syncthreads();
        As[ak + 0][ar] = av.x; As[ak + 1][ar] = av.y;
        As[ak + 2][ar] = av.z; As[ak + 3][ar] = av.w;
        Bs[ak + 0][ar] = bv.x; Bs[ak + 1][ar] = bv.y;
        Bs[ak + 2][ar] = bv.z; Bs[ak + 3][ar] = bv.w;
        __syncthreads();
        if (kt + 8 < KK) {
            av = *(const float4*)(xp + kt + 8);   // prefetch overlaps compute
            bv = *(const float4*)(yp + kt + 8);
        }
        #pragma unroll
        for (int k = 0; k < 8; ++k) {
            float a[8], b[8];
            *(float4*)(a)     = *(const float4*)&As[k][ty * 8];
            *(float4*)(a + 4) = *(const float4*)&As[k][ty * 8 + 4];
            *(float4*)(b)     = *(const float4*)&Bs[k][tx * 8];
            *(float4*)(b + 4) = *(const float4*)&Bs[k][tx * 8 + 4];
            #pragma unroll
            for (int i = 0; i < 8; ++i)
                #pragma unroll
                for (int j = 0; j < 8; ++j)
                    acc[i][j] = fmaf(a[i], b[j], acc[i][j]);
        }
    }

    const int gi0 = by * 128 + ty * 8;
    const int gj0 = bx * 128 + tx * 8;
    float yv[8];
    #pragma unroll
    for (int j = 0; j < 8; ++j) yv[j] = g_ys[gj0 + j];
    #pragma unroll
    for (int i = 0; i < 8; ++i) {
        float xs = g_xs[gi0 + i];
        float4 o0, o1;
        o0.x = (xs + yv[0] - 2.f * acc[i][0]) * SCALEF;
        o0.y = (xs + yv[1] - 2.f * acc[i][1]) * SCALEF;
        o0.z = (xs + yv[2] - 2.f * acc[i][2]) * SCALEF;
        o0.w = (xs + yv[3] - 2.f * acc[i][3]) * SCALEF;
        o1.x = (xs + yv[4] - 2.f * acc[i][4]) * SCALEF;
        o1.y = (xs + yv[5] - 2.f * acc[i][5]) * SCALEF;
        o1.z = (xs + yv[6] - 2.f * acc[i][6]) * SCALEF;
        o1.w = (xs + yv[7] - 2.f * acc[i][7]) * SCALEF;
        float* dst = g_C2 + (size_t)(gi0 + i) * NN + gj0;
        *(float4*)(dst)     = o0;
        *(float4*)(dst + 4) = o1;
        H8 hh;
        hh.h[0] = __floats2half2_rn(o0.x, o0.y);
        hh.h[1] = __floats2half2_rn(o0.z, o0.w);
        hh.h[2] = __floats2half2_rn(o1.x, o1.y);
        hh.h[3] = __floats2half2_rn(o1.z, o1.w);
        *(uint4*)&g_Ch[(size_t)(gi0 + i) * NN + gj0] = hh.u;
    }
}

// ---------------------------------------------------------------------------
__global__ __launch_bounds__(THREADS, 1) void sinkhorn_persistent(int NB, float* __restrict__ out) {
    const int tid = threadIdx.x;
    const int bid = blockIdx.x;
    const int lane = tid & 31;
    const int wid = tid >> 5;

    __shared__ __align__(16) float  svec[NN];    // 16 KB fp32 potentials
    __shared__ __align__(16) __half svech[NN];   // 8 KB fp16 potentials
    __shared__ float sm_m[64][33];
    __shared__ float sm_s[64][33];
    __shared__ float sshift[32];
    __shared__ int   sfail;
    __shared__ float sred[32];

    const __half2 NEGINF2 = __float2half2_rn(-60000.f);

    for (int it = 0; it < N_ITER; ++it) {
        // ---- u-pass: warp-per-row; fp16 scan, fp32 exp for survivors ----
        for (int i = tid; i < NN; i += THREADS) {
            float t = g_v[i];
            svec[i] = t;
            svech[i] = __float2half(t);
        }
        __syncthreads();

        for (int row = bid + wid * NB; row < NN; row += 32 * NB) {
            const uint4* Chp = (const uint4*)(g_Ch + (size_t)row * NN) + lane;
            const float* Crow = g_C2 + (size_t)row * NN;
            float shift = g_mu[row];
            float Mrun, Ssum;
            #pragma unroll 1
            for (int attempt = 0; attempt < 4; ++attempt) {
                __half2 mrun2 = NEGINF2;
                float s = 0.f;
                const float thr = shift - TH_SKIP;
                #pragma unroll 1
                for (int c0 = 0; c0 < 16; ++c0) {
                    H8 Ch; Ch.u = __ldg(Chp + (c0 << 5));
                    H8 Vh; Vh.u = *(const uint4*)&svech[(c0 << 8) + (lane << 3)];
                    __half2 t0 = __hsub2(Vh.h[0], Ch.h[0]);
                    __half2 t1 = __hsub2(Vh.h[1], Ch.h[1]);
                    __half2 t2 = __hsub2(Vh.h[2], Ch.h[2]);
                    __half2 t3 = __hsub2(Vh.h[3], Ch.h[3]);
                    __half2 m2 = __hmax2(__hmax2(t0, t1), __hmax2(t2, t3));
                    mrun2 = __hmax2(mrun2, m2);
                    float mc = fmaxf(__low2float(m2), __high2float(m2));
                    if (__any_sync(0xffffffffu, mc >= thr)) {
                        int c = (c0 << 8) + lane * 4 * 2;     // 8 elems/lane
                        float4 C0 = __ldg((const float4*)(Crow + c));
                        float4 C1 = __ldg((const float4*)(Crow + c + 4));
                        const float* vp = &svec[c];
                        float a0 = vp[0] - C0.x - shift, a1 = vp[1] - C0.y - shift;
                        float a2 = vp[2] - C0.z - shift, a3 = vp[3] - C0.w - shift;
                        float a4 = vp[4] - C1.x - shift, a5 = vp[5] - C1.y - shift;
                        float a6 = vp[6] - C1.z - shift, a7 = vp[7] - C1.w - shift;
                        s += ((ex2f(fminf(a0, CLAMP)) + ex2f(fminf(a1, CLAMP)))
                            + (ex2f(fminf(a2, CLAMP)) + ex2f(fminf(a3, CLAMP))))
                           + ((ex2f(fminf(a4, CLAMP)) + ex2f(fminf(a5, CLAMP)))
                            + (ex2f(fminf(a6, CLAMP)) + ex2f(fminf(a7, CLAMP))));
                    }
                }
                Mrun = fmaxf(__low2float(mrun2), __high2float(mrun2));
                Ssum = s;
                #pragma unroll
                for (int o = 16; o; o >>= 1) {
                    Mrun = fmaxf(Mrun, __shfl_xor_sync(0xffffffffu, Mrun, o));
                    Ssum += __shfl_xor_sync(0xffffffffu, Ssum, o);
                }
                if (Mrun >= shift - TH_LO && Mrun <= shift + TH_HI) break;
                shift = Mrun;
            }
            if (lane == 0) {
                g_u[row] = -(shift + lg2f(Ssum));
                g_mu[row] = Mrun;
            }
        }
        grid_sync(NB);

        // ---- v-pass: group of 32 cols; lane owns a column pair (half2) ----
        for (int i = tid; i < NN; i += THREADS) {
            float t = g_u[i];
            svec[i] = t;
            svech[i] = __float2half(t);
        }
        __syncthreads();
        for (int g = bid; g < NN / 32; g += NB) {
            const int j0 = g << 5;
            const int cp = lane & 15;             // column pair
            const int sub = lane >> 4;            // row substratum
            const int r = (wid << 1) + sub;       // stratum 0..63
            if (tid < 32) sshift[tid] = g_mv[j0 + tid];
            if (tid == 0) sfail = 0;
            __syncthreads();
            #pragma unroll 1
            for (int attempt = 0; attempt < 4; ++attempt) {
                const float shift_lo = sshift[2 * cp];
                const float shift_hi = sshift[2 * cp + 1];
                const float thr_lo = shift_lo - TH_SKIP;
                const float thr_hi = shift_hi - TH_SKIP;
                __half2 mrun2 = NEGINF2;
                float s_lo = 0.f, s_hi = 0.f;
                #pragma unroll 1
                for (int q0 = 0; q0 < NN; q0 += 1024) {
                    const int row0 = q0 + r;
                    __half2 m2 = NEGINF2;
                    #pragma unroll
                    for (int k = 0; k < 16; ++k) {
                        int row = row0 + (k << 6);
                        __half2 c2 = __ldg((const __half2*)(g_Ch + (size_t)row * NN + j0 + 2 * cp));
                        __half2 u2 = __half2half2(svech[row]);
                        m2 = __hmax2(m2, __hsub2(u2, c2));
                    }
                    mrun2 = __hmax2(mrun2, m2);
                    bool surv = (__low2float(m2) >= thr_lo) || (__high2float(m2) >= thr_hi);
                    if (__any_sync(0xffffffffu, surv)) {
                        #pragma unroll
                        for (int k = 0; k < 16; ++k) {
                            int row = row0 + (k << 6);
                            float2 cf = *(const float2*)(g_C2 + (size_t)row * NN + j0 + 2 * cp);
                            float uf = svec[row];
                            s_lo += ex2f(fminf(uf - cf.x - shift_lo, CLAMP));
                            s_hi += ex2f(fminf(uf - cf.y - shift_hi, CLAMP));
                        }
                    }
                }
                sm_m[r][2 * cp]     = __low2float(mrun2);
                sm_m[r][2 * cp + 1] = __high2float(mrun2);
                sm_s[r][2 * cp]     = s_lo;
                sm_s[r][2 * cp + 1] = s_hi;
                __syncthreads();
                {   // warp wid merges 64 strata of column wid
                    float mm = fmaxf(sm_m[lane][wid], sm_m[lane + 32][wid]);
                    float ss = sm_s[lane][wid] + sm_s[lane + 32][wid];
                    #pragma unroll
                    for (int o = 16; o; o >>= 1) {
                        mm = fmaxf(mm, __shfl_xor_sync(0xffffffffu, mm, o));
                        ss += __shfl_xor_sync(0xffffffffu, ss, o);
                    }
                    float sc = sshift[wid];
                    bool ok = (mm >= sc - TH_LO && mm <= sc + TH_HI);
                    if (lane == 0) {
                        if (ok) {
                            g_v[j0 + wid] = -(sc + lg2f(ss));
                            g_mv[j0 + wid] = mm;
                        } else {
                            sshift[wid] = mm;
                            sfail = 1;
                        }
                    }
                }
                __syncthreads();
                if (!sfail) break;
                if (tid == 0) sfail = 0;
                __syncthreads();
            }
            __syncthreads();
        }
        grid_sync(NB);
    }

    // ---- final cost: sum P*C / N  (warp-per-row, full fp32 exp) ----
    {
        for (int i = tid; i < NN; i += THREADS) svec[i] = g_v[i];
        __syncthreads();
        float acc = 0.f;
        for (int row = bid + wid * NB; row < NN; row += 32 * NB) {
            const float u2 = g_u[row];
            const float* Crow = g_C2 + (size_t)row * NN;
            #pragma unroll 4
            for (int c0 = 0; c0 < NN; c0 += 128) {
                int cc = c0 + lane * 4;
                float4 C4 = __ldg((const float4*)(Crow + cc));
                float4 V4 = *(const float4*)&svec[cc];
                acc = fmaf(ex2f(u2 + V4.x - C4.x), C4.x, acc);
                acc = fmaf(ex2f(u2 + V4.y - C4.y), C4.y, acc);
                acc = fmaf(ex2f(u2 + V4.z - C4.z), C4.z, acc);
                acc = fmaf(ex2f(u2 + V4.w - C4.w), C4.w, acc);
            }
        }
        #pragma unroll
        for (int o = 16; o; o >>= 1) acc += __shfl_xor_sync(0xffffffffu, acc, o);
        __syncthreads();
        if (lane == 0) sred[wid] = acc;
        __syncthreads();
        if (wid == 0) {
            float s = sred[lane];
            #pragma unroll
            for (int o = 16; o; o >>= 1) s += __shfl_xor_sync(0xffffffffu, s, o);
            if (lane == 0) g_dpart[bid] = (double)s;
        }
        grid_sync(NB);
        if (bid == 0 && tid == 0) {
            double S = 0.0;
            for (int b = 0; b < NB; ++b) S += g_dpart[b];
            out[0] = (float)(S / ((double)SCALEF * (double)NN));
        }
    }
}

// ---------------------------------------------------------------------------
extern "C" void kernel_launch(void* const* d_in, const int* in_sizes, int n_in,
                              void* d_out, int out_size) {
    const float* x = (const float*)d_in[0];
    const float* y = (const float*)d_in[1];
    float* out = (float*)d_out;

    int dev = 0;
    cudaGetDevice(&dev);
    int sm = 148;
    cudaDeviceGetAttribute(&sm, cudaDevAttrMultiProcessorCount, dev);
    int NB = sm < NBMAX ? sm : NBMAX;

    sqnorm_kernel<<<1024, 256>>>(x, y);
    init_kernel<<<16, 256>>>();
    gemm_kernel<<<dim3(32, 32), 256>>>(x, y);
    sinkhorn_persistent<<<NB, THREADS>>>(NB, out);
}

// round 16
// speedup vs baseline: 1.3000x; 1.1896x over previous
#include <cuda_runtime.h>
#include <math.h>

// Sinkhorn distance, N=M=4096, D=256, EPS=0.1, 100 iterations.
// R16 = R11 (best: lazy-LSE, atomic grid barrier) + u-pass 512-elem
// super-chunks (4 LDG.128 in flight, halved latency chain) + GEMM k-prefetch.

#define NN 4096
#define KK 256
#define SCALEF 14.4269504088896340736f   // log2(e)/EPS
#define NEG_BIG (-1e30f)
#define THREADS 1024
#define NBMAX 160
#define N_ITER 100
#define TH_SKIP 40.f
#define TH_LO   10.f
#define TH_HI   50.f
#define CLAMP   80.f

__device__ __align__(16) float g_C2[(size_t)NN * NN];     // 64 MB: C * SCALEF
__device__ __align__(16) float g_u[NN];
__device__ __align__(16) float g_v[NN];
__device__ __align__(16) float g_mu[NN];                  // row max estimate
__device__ __align__(16) float g_mv[NN];                  // col max estimate
__device__ float g_xs[NN];
__device__ float g_ys[NN];
__device__ double g_dpart[NBMAX];

__device__ unsigned g_bar_count;
__device__ volatile unsigned g_bar_gen;

__device__ __forceinline__ float ex2f(float x) {
    float r; asm("ex2.approx.ftz.f32 %0, %1;" : "=f"(r) : "f"(x)); return r;
}
__device__ __forceinline__ float lg2f(float x) {
    float r; asm("lg2.approx.ftz.f32 %0, %1;" : "=f"(r) : "f"(x)); return r;
}

// R11 atomic barrier (single-line spin; proven).
__device__ __forceinline__ void grid_sync(int NB) {
    __syncthreads();
    if (threadIdx.x == 0) {
        unsigned gen = g_bar_gen;
        __threadfence();
        unsigned t = atomicAdd(&g_bar_count, 1u);
        if (t == (unsigned)(NB - 1)) {
            g_bar_count = 0;
            __threadfence();
            g_bar_gen = gen + 1;
        } else {
            while (g_bar_gen == gen) { }
        }
        __threadfence();
    }
    __syncthreads();
}

// ---------------------------------------------------------------------------
__global__ __launch_bounds__(256) void sqnorm_kernel(const float* __restrict__ X,
                                                     const float* __restrict__ Y) {
    int gw = (blockIdx.x * 256 + threadIdx.x) >> 5;
    int lane = threadIdx.x & 31;
    const float* src = (gw < NN) ? (X + (size_t)gw * KK) : (Y + (size_t)(gw - NN) * KK);
    float s = 0.f;
    #pragma unroll
    for (int c = 0; c < KK; c += 32) {
        float a = src[c + lane];
        s = fmaf(a, a, s);
    }
    #pragma unroll
    for (int o = 16; o; o >>= 1) s += __shfl_xor_sync(0xffffffffu, s, o);
    if (lane == 0) {
        if (gw < NN) g_xs[gw] = s; else g_ys[gw - NN] = s;
    }
}

__global__ void init_kernel() {
    int i = blockIdx.x * 256 + threadIdx.x;
    if (i < NN) { g_v[i] = 0.f; g_mu[i] = NEG_BIG; g_mv[i] = NEG_BIG; }
    if (i == 0) { g_bar_count = 0; g_bar_gen = 0; }
}

// ---------------------------------------------------------------------------
// C2 = (|x|^2 + |y|^2 - 2 x.y) * SCALEF  (fp32 FFMA GEMM, k-tile prefetch)
__global__ __launch_bounds__(256) void gemm_kernel(const float* __restrict__ X,
                                                   const float* __restrict__ Y) {
    __shared__ float As[8][128];
    __shared__ float Bs[8][128];
    const int tid = threadIdx.x;
    const int bx = blockIdx.x;
    const int by = blockIdx.y;
    const int ar = tid >> 1;
    const int ak = (tid & 1) * 4;
    const int tx = tid & 15;
    const int ty = tid >> 4;

    const float* xp = X + (size_t)(by * 128 + ar) * KK + ak;
    const float* yp = Y + (size_t)(bx * 128 + ar) * KK + ak;

    float acc[8][8];
    #pragma unroll
    for (int i = 0; i < 8; ++i)
        #pragma unroll
        for (int j = 0; j < 8; ++j) acc[i][j] = 0.f;

    float4 av = *(const float4*)(xp);
    float4 bv = *(const float4*)(yp);

    for (int kt = 0; kt < KK; kt += 8) {
        __syncthreads();
        As[ak + 0][ar] = av.x; As[ak + 1][ar] = av.y;
        As[ak + 2][ar] = av.z; As[ak + 3][ar] = av.w;
        Bs[ak + 0][ar] = bv.x; Bs[ak + 1][ar] = bv.y;
        Bs[ak + 2][ar] = bv.z; Bs[ak + 3][ar] = bv.w;
        __syncthreads();
        if (kt + 8 < KK) {
            av = *(const float4*)(xp + kt + 8);   // prefetch overlaps compute
            bv = *(const float4*)(yp + kt + 8);
        }
        #pragma unroll
        for (int k = 0; k < 8; ++k) {
            float a[8], b[8];
            *(float4*)(a)     = *(const float4*)&As[k][ty * 8];
            *(float4*)(a + 4) = *(const float4*)&As[k][ty * 8 + 4];
            *(float4*)(b)     = *(const float4*)&Bs[k][tx * 8];
            *(float4*)(b + 4) = *(const float4*)&Bs[k][tx * 8 + 4];
            #pragma unroll
            for (int i = 0; i < 8; ++i)
                #pragma unroll
                for (int j = 0; j < 8; ++j)
                    acc[i][j] = fmaf(a[i], b[j], acc[i][j]);
        }
    }

    const int gi0 = by * 128 + ty * 8;
    const int gj0 = bx * 128 + tx * 8;
    float yv[8];
    #pragma unroll
    for (int j = 0; j < 8; ++j) yv[j] = g_ys[gj0 + j];
    #pragma unroll
    for (int i = 0; i < 8; ++i) {
        float xs = g_xs[gi0 + i];
        float4 o0, o1;
        o0.x = (xs + yv[0] - 2.f * acc[i][0]) * SCALEF;
        o0.y = (xs + yv[1] - 2.f * acc[i][1]) * SCALEF;
        o0.z = (xs + yv[2] - 2.f * acc[i][2]) * SCALEF;
        o0.w = (xs + yv[3] - 2.f * acc[i][3]) * SCALEF;
        o1.x = (xs + yv[4] - 2.f * acc[i][4]) * SCALEF;
        o1.y = (xs + yv[5] - 2.f * acc[i][5]) * SCALEF;
        o1.z = (xs + yv[6] - 2.f * acc[i][6]) * SCALEF;
        o1.w = (xs + yv[7] - 2.f * acc[i][7]) * SCALEF;
        float* dst = g_C2 + (size_t)(gi0 + i) * NN + gj0;
        *(float4*)(dst)     = o0;
        *(float4*)(dst + 4) = o1;
    }
}

// ---------------------------------------------------------------------------
// one 256-elem scan/vote/exp sub-block (values already in registers)
#define SUBCHUNK(Ca, Cb, off)                                                  \
    {                                                                          \
        float4 V0 = *(const float4*)&svec[(off)];                              \
        float4 V1 = *(const float4*)&svec[(off) + 128];                        \
        float t0 = V0.x - Ca.x, t1 = V0.y - Ca.y;                              \
        float t2 = V0.z - Ca.z, t3 = V0.w - Ca.w;                              \
        float t4 = V1.x - Cb.x, t5 = V1.y - Cb.y;                              \
        float t6 = V1.z - Cb.z, t7 = V1.w - Cb.w;                              \
        float mc = fmaxf(fmaxf(fmaxf(t0, t1), fmaxf(t2, t3)),                  \
                         fmaxf(fmaxf(t4, t5), fmaxf(t6, t7)));                 \
        mrun = fmaxf(mrun, mc);                                                \
        if (__any_sync(0xffffffffu, mc >= thr)) {                              \
            s += ((ex2f(fminf(t0 - shift, CLAMP)) + ex2f(fminf(t1 - shift, CLAMP)))  \
                + (ex2f(fminf(t2 - shift, CLAMP)) + ex2f(fminf(t3 - shift, CLAMP)))) \
               + ((ex2f(fminf(t4 - shift, CLAMP)) + ex2f(fminf(t5 - shift, CLAMP)))  \
                + (ex2f(fminf(t6 - shift, CLAMP)) + ex2f(fminf(t7 - shift, CLAMP))));\
        }                                                                      \
    }

__global__ __launch_bounds__(THREADS, 1) void sinkhorn_persistent(int NB, float* __restrict__ out) {
    const int tid = threadIdx.x;
    const int bid = blockIdx.x;
    const int lane = tid & 31;
    const int wid = tid >> 5;

    __shared__ float svec[NN];          // 16 KB: dual-potential cache
    __shared__ float sm_m[32][33];
    __shared__ float sm_s[32][33];
    __shared__ float sshift[32];
    __shared__ int   sfail;
    __shared__ float sred[32];

    for (int it = 0; it < N_ITER; ++it) {
        // ---- u-pass: warp-per-row, lazy LSE, 512-elem super-chunks ----
        for (int i = tid; i < NN; i += THREADS) svec[i] = g_v[i];
        __syncthreads();

        for (int row = bid + wid * NB; row < NN; row += 32 * NB) {
            const float* Crow = g_C2 + (size_t)row * NN;
            float shift = g_mu[row];
            float Mrun, Ssum;
            #pragma unroll 1
            for (int attempt = 0; attempt < 4; ++attempt) {
                float mrun = NEG_BIG, s = 0.f;
                const float thr = shift - TH_SKIP;
                #pragma unroll 1
                for (int c0 = 0; c0 < NN; c0 += 512) {
                    int c = c0 + lane * 4;
                    float4 Ca = __ldg((const float4*)(Crow + c));
                    float4 Cb = __ldg((const float4*)(Crow + c + 128));
                    float4 Cc = __ldg((const float4*)(Crow + c + 256));
                    float4 Cd = __ldg((const float4*)(Crow + c + 384));
                    SUBCHUNK(Ca, Cb, c)
                    SUBCHUNK(Cc, Cd, c + 256)
                }
                Mrun = mrun; Ssum = s;
                #pragma unroll
                for (int o = 16; o; o >>= 1) {
                    Mrun = fmaxf(Mrun, __shfl_xor_sync(0xffffffffu, Mrun, o));
                    Ssum += __shfl_xor_sync(0xffffffffu, Ssum, o);
                }
                if (Mrun >= shift - TH_LO && Mrun <= shift + TH_HI) break;
                shift = Mrun;
            }
            if (lane == 0) {
                g_u[row] = -(shift + lg2f(Ssum));
                g_mu[row] = Mrun;
            }
        }
        grid_sync(NB);

        // ---- v-pass: CTA owns 32 columns; lazy LSE (unchanged from R11) ----
        for (int i = tid; i < NN; i += THREADS) svec[i] = g_u[i];
        __syncthreads();
        for (int g = bid; g < NN / 32; g += NB) {
            const int j0 = g << 5;
            const int c = lane;
            const int r = wid;
            if (tid < 32) sshift[tid] = g_mv[j0 + tid];
            if (tid == 0) sfail = 0;
            __syncthreads();
            #pragma unroll 1
            for (int attempt = 0; attempt < 4; ++attempt) {
                float shift = sshift[c];
                const float thr = shift - TH_SKIP;
                float mrun = NEG_BIG, s = 0.f;
                #pragma unroll 1
                for (int q0 = 0; q0 < NN; q0 += 512) {
                    const float* p = g_C2 + (size_t)(q0 + r) * NN + j0 + c;
                    const float* up = &svec[q0 + r];
                    float t[16];
                    #pragma unroll
                    for (int k = 0; k < 16; ++k)
                        t[k] = up[k << 5] - __ldg(p + ((size_t)k << 5) * NN);
                    float mc = t[0];
                    #pragma unroll
                    for (int k = 1; k < 16; ++k) mc = fmaxf(mc, t[k]);
                    mrun = fmaxf(mrun, mc);
                    if (__any_sync(0xffffffffu, mc >= thr)) {
                        float e = 0.f;
                        #pragma unroll
                        for (int k = 0; k < 16; ++k)
                            e += ex2f(fminf(t[k] - shift, CLAMP));
                        s += e;
                    }
                }
                sm_m[r][c] = mrun;
                sm_s[r][c] = s;
                __syncthreads();
                {   // warp wid merges column wid (plain sum: common shift)
                    float mm = sm_m[lane][wid];
                    float ss = sm_s[lane][wid];
                    #pragma unroll
                    for (int o = 16; o; o >>= 1) {
                        mm = fmaxf(mm, __shfl_xor_sync(0xffffffffu, mm, o));
                        ss += __shfl_xor_sync(0xffffffffu, ss, o);
                    }
                    float sc = sshift[wid];
                    bool ok = (mm >= sc - TH_LO && mm <= sc + TH_HI);
                    if (lane == 0) {
                        if (ok) {
                            g_v[j0 + wid] = -(sc + lg2f(ss));
                            g_mv[j0 + wid] = mm;
                        } else {
                            sshift[wid] = mm;
                            sfail = 1;
                        }
                    }
                }
                __syncthreads();
                if (!sfail) break;
                if (tid == 0) sfail = 0;
                __syncthreads();
            }
            __syncthreads();
        }
        grid_sync(NB);
    }

    // ---- final cost: sum P*C / N  (warp-per-row, full exp) ----
    {
        for (int i = tid; i < NN; i += THREADS) svec[i] = g_v[i];
        __syncthreads();
        float acc = 0.f;
        for (int row = bid + wid * NB; row < NN; row += 32 * NB) {
            const float u2 = g_u[row];
            const float* Crow = g_C2 + (size_t)row * NN;
            #pragma unroll 4
            for (int c0 = 0; c0 < NN; c0 += 128) {
                int cc = c0 + lane * 4;
                float4 C4 = __ldg((const float4*)(Crow + cc));
                float4 V4 = *(const float4*)&svec[cc];
                acc = fmaf(ex2f(u2 + V4.x - C4.x), C4.x, acc);
                acc = fmaf(ex2f(u2 + V4.y - C4.y), C4.y, acc);
                acc = fmaf(ex2f(u2 + V4.z - C4.z), C4.z, acc);
                acc = fmaf(ex2f(u2 + V4.w - C4.w), C4.w, acc);
            }
        }
        #pragma unroll
        for (int o = 16; o; o >>= 1) acc += __shfl_xor_sync(0xffffffffu, acc, o);
        __syncthreads();
        if (lane == 0) sred[wid] = acc;
        __syncthreads();
        if (wid == 0) {
            float s = sred[lane];
            #pragma unroll
            for (int o = 16; o; o >>= 1) s += __shfl_xor_sync(0xffffffffu, s, o);
            if (lane == 0) g_dpart[bid] = (double)s;
        }
        grid_sync(NB);
        if (bid == 0 && tid == 0) {
            double S = 0.0;
            for (int b = 0; b < NB; ++b) S += g_dpart[b];
            out[0] = (float)(S / ((double)SCALEF * (double)NN));
        }
    }
}

// ---------------------------------------------------------------------------
extern "C" void kernel_launch(void* const* d_in, const int* in_sizes, int n_in,
                              void* d_out, int out_size) {
    const float* x = (const float*)d_in[0];
    const float* y = (const float*)d_in[1];
    float* out = (float*)d_out;

    int dev = 0;
    cudaGetDevice(&dev);
    int sm = 148;
    cudaDeviceGetAttribute(&sm, cudaDevAttrMultiProcessorCount, dev);
    int NB = sm < NBMAX ? sm : NBMAX;

    sqnorm_kernel<<<1024, 256>>>(x, y);
    init_kernel<<<16, 256>>>();
    gemm_kernel<<<dim3(32, 32), 256>>>(x, y);
    sinkhorn_persistent<<<NB, THREADS>>>(NB, out);
}